// round 4
// baseline (speedup 1.0000x reference)
#include <cuda_runtime.h>
#include <cuda_bf16.h>

// out[b,h,i,j] = in[b,h,i,j] + slope[h] * (j - (S-1)),  slope[h] = 2^(-0.5*(h+1))
// Shape: (2, 16, 2048, 2048) fp32. Pure HBM-streaming elementwise add.
//
// R4: persistent grid-stride — 2048 resident blocks x 16 exact iterations,
//     VPT=4 front-batched LDG.128 per iteration, streaming hints.

static constexpr int SEQ = 2048;
static constexpr unsigned long long ROW_MASK = SEQ - 1;
static constexpr int HEAD_SHIFT = 22;        // 2048*2048 elems per head-plane
static constexpr int HEAD_MASK = 15;
static constexpr int VPT = 4;                // float4s per thread per iteration
static constexpr unsigned int BLOCK = 256;
static constexpr unsigned int GRID = 2048;
static constexpr unsigned int CHUNK = BLOCK * VPT;   // 1024 float4s per block-iter
static constexpr int ITERS = 16;             // 2^25 / (2048*1024)

__global__ void __launch_bounds__(256)
alibi_add_kernel(const float4* __restrict__ in, float4* __restrict__ out) {
#pragma unroll 1
    for (int it = 0; it < ITERS; it++) {
        unsigned int chunk = blockIdx.x + (unsigned int)it * GRID;
        unsigned int base  = chunk * CHUNK + threadIdx.x;

        float4 v[VPT];
#pragma unroll
        for (int k = 0; k < VPT; k++) {
            v[k] = __ldcs(&in[base + k * BLOCK]);   // front-batched loads
        }

#pragma unroll
        for (int k = 0; k < VPT; k++) {
            unsigned int idx = base + k * BLOCK;
            unsigned long long e = (unsigned long long)idx * 4ull;
            int j = (int)(e & ROW_MASK);
            int h = (int)((e >> HEAD_SHIFT) & HEAD_MASK);

            float slope = exp2f(-0.5f * (float)(h + 1));
            float d0 = (float)(j - (SEQ - 1));

            float4 r = v[k];
            r.x = fmaf(slope, d0,        r.x);
            r.y = fmaf(slope, d0 + 1.0f, r.y);
            r.z = fmaf(slope, d0 + 2.0f, r.z);
            r.w = fmaf(slope, d0 + 3.0f, r.w);
            __stcs(&out[idx], r);
        }
    }
}

extern "C" void kernel_launch(void* const* d_in, const int* in_sizes, int n_in,
                              void* d_out, int out_size) {
    const float4* in = (const float4*)d_in[0];
    float4* out = (float4*)d_out;
    alibi_add_kernel<<<GRID, BLOCK>>>(in, out);
}

// round 5
// speedup vs baseline: 1.0374x; 1.0374x over previous
#include <cuda_runtime.h>
#include <cuda_bf16.h>

// out[b,h,i,j] = in[b,h,i,j] + slope[h] * (j - (S-1)),  slope[h] = 2^(-0.5*(h+1))
// Shape: (2, 16, 2048, 2048) fp32. Pure HBM-streaming elementwise add.
//
// R5: Blackwell 256-bit global ld/st (ld/st.global.cs.v8.f32), one-shot grid,
//     2 front-batched v8 loads per thread (16 floats), 32768 blocks x 256.

static constexpr int SEQ = 2048;
static constexpr unsigned long long ROW_MASK8 = (SEQ / 8) - 1;  // v8 slots per row
static constexpr int HEAD_SHIFT8 = 22 - 3;   // head plane = 2^22 elems = 2^19 v8 slots
static constexpr int HEAD_MASK = 15;
static constexpr int VPT8 = 2;               // v8 (32B) slots per thread
static constexpr unsigned int BLOCK = 256;

struct F8 { float a0,a1,a2,a3,a4,a5,a6,a7; };

__device__ __forceinline__ F8 ldg_cs_v8(const float* p) {
    F8 r;
    asm volatile("ld.global.cs.v8.f32 {%0,%1,%2,%3,%4,%5,%6,%7}, [%8];"
                 : "=f"(r.a0), "=f"(r.a1), "=f"(r.a2), "=f"(r.a3),
                   "=f"(r.a4), "=f"(r.a5), "=f"(r.a6), "=f"(r.a7)
                 : "l"(p));
    return r;
}

__device__ __forceinline__ void stg_cs_v8(float* p, const F8& r) {
    asm volatile("st.global.cs.v8.f32 [%0], {%1,%2,%3,%4,%5,%6,%7,%8};"
                 :: "l"(p),
                    "f"(r.a0), "f"(r.a1), "f"(r.a2), "f"(r.a3),
                    "f"(r.a4), "f"(r.a5), "f"(r.a6), "f"(r.a7)
                 : "memory");
}

__global__ void __launch_bounds__(256)
alibi_add_kernel(const float* __restrict__ in, float* __restrict__ out) {
    // Block covers contiguous BLOCK*VPT8 v8-slots; thread t owns slot base+t
    // and base+t+BLOCK. Consecutive threads -> consecutive 32B: coalesced.
    unsigned int base = blockIdx.x * (BLOCK * VPT8) + threadIdx.x;

    F8 v[VPT8];
#pragma unroll
    for (int k = 0; k < VPT8; k++) {
        v[k] = ldg_cs_v8(in + (unsigned long long)(base + k * BLOCK) * 8ull);
    }

#pragma unroll
    for (int k = 0; k < VPT8; k++) {
        unsigned int slot = base + k * BLOCK;
        int j8 = (int)(slot & ROW_MASK8);                 // v8-slot within row
        int h  = (int)((slot >> HEAD_SHIFT8) & HEAD_MASK);

        float slope = exp2f(-0.5f * (float)(h + 1));
        float d0 = (float)(j8 * 8 - (SEQ - 1));           // distance of element 0

        F8 r = v[k];
        r.a0 = fmaf(slope, d0,        r.a0);
        r.a1 = fmaf(slope, d0 + 1.0f, r.a1);
        r.a2 = fmaf(slope, d0 + 2.0f, r.a2);
        r.a3 = fmaf(slope, d0 + 3.0f, r.a3);
        r.a4 = fmaf(slope, d0 + 4.0f, r.a4);
        r.a5 = fmaf(slope, d0 + 5.0f, r.a5);
        r.a6 = fmaf(slope, d0 + 6.0f, r.a6);
        r.a7 = fmaf(slope, d0 + 7.0f, r.a7);
        stg_cs_v8(out + (unsigned long long)slot * 8ull, r);
    }
}

extern "C" void kernel_launch(void* const* d_in, const int* in_sizes, int n_in,
                              void* d_out, int out_size) {
    const float* in = (const float*)d_in[0];
    float* out = (float*)d_out;
    unsigned int n8 = (unsigned int)(out_size / 8);       // 16777216 v8 slots
    unsigned int grid = n8 / (BLOCK * VPT8);              // 32768 blocks (exact)
    alibi_add_kernel<<<grid, BLOCK>>>(in, out);
}

// round 6
// speedup vs baseline: 1.0389x; 1.0014x over previous
#include <cuda_runtime.h>
#include <cuda_bf16.h>

// out[b,h,i,j] = in[b,h,i,j] + slope[h] * (j - (S-1)),  slope[h] = 2^(-0.5*(h+1))
// Shape: (2, 16, 2048, 2048) fp32. Pure HBM-streaming elementwise add.
//
// R6: 256-bit global accesses; loads .cs (evict-first, read-once), stores
//     default .wb (let L2 batch dirty lines -> fewer HBM bus turnarounds).
//     VPT8=2, 256 threads, 32768 one-shot blocks.

static constexpr int SEQ = 2048;
static constexpr unsigned long long ROW_MASK8 = (SEQ / 8) - 1;  // v8 slots per row
static constexpr int HEAD_SHIFT8 = 22 - 3;   // head plane = 2^19 v8 slots
static constexpr int HEAD_MASK = 15;
static constexpr int VPT8 = 2;               // 32B slots per thread
static constexpr unsigned int BLOCK = 256;

struct F8 { float a0,a1,a2,a3,a4,a5,a6,a7; };

__device__ __forceinline__ F8 ldg_cs_v8(const float* p) {
    F8 r;
    asm volatile("ld.global.cs.v8.f32 {%0,%1,%2,%3,%4,%5,%6,%7}, [%8];"
                 : "=f"(r.a0), "=f"(r.a1), "=f"(r.a2), "=f"(r.a3),
                   "=f"(r.a4), "=f"(r.a5), "=f"(r.a6), "=f"(r.a7)
                 : "l"(p));
    return r;
}

__device__ __forceinline__ void stg_wb_v8(float* p, const F8& r) {
    asm volatile("st.global.v8.f32 [%0], {%1,%2,%3,%4,%5,%6,%7,%8};"
                 :: "l"(p),
                    "f"(r.a0), "f"(r.a1), "f"(r.a2), "f"(r.a3),
                    "f"(r.a4), "f"(r.a5), "f"(r.a6), "f"(r.a7)
                 : "memory");
}

__global__ void __launch_bounds__(256)
alibi_add_kernel(const float* __restrict__ in, float* __restrict__ out) {
    unsigned int base = blockIdx.x * (BLOCK * VPT8) + threadIdx.x;

    F8 v[VPT8];
#pragma unroll
    for (int k = 0; k < VPT8; k++) {
        v[k] = ldg_cs_v8(in + (unsigned long long)(base + k * BLOCK) * 8ull);
    }

#pragma unroll
    for (int k = 0; k < VPT8; k++) {
        unsigned int slot = base + k * BLOCK;
        int j8 = (int)(slot & ROW_MASK8);
        int h  = (int)((slot >> HEAD_SHIFT8) & HEAD_MASK);

        float slope = exp2f(-0.5f * (float)(h + 1));
        float d0 = (float)(j8 * 8 - (SEQ - 1));

        F8 r = v[k];
        r.a0 = fmaf(slope, d0,        r.a0);
        r.a1 = fmaf(slope, d0 + 1.0f, r.a1);
        r.a2 = fmaf(slope, d0 + 2.0f, r.a2);
        r.a3 = fmaf(slope, d0 + 3.0f, r.a3);
        r.a4 = fmaf(slope, d0 + 4.0f, r.a4);
        r.a5 = fmaf(slope, d0 + 5.0f, r.a5);
        r.a6 = fmaf(slope, d0 + 6.0f, r.a6);
        r.a7 = fmaf(slope, d0 + 7.0f, r.a7);
        stg_wb_v8(out + (unsigned long long)slot * 8ull, r);
    }
}

extern "C" void kernel_launch(void* const* d_in, const int* in_sizes, int n_in,
                              void* d_out, int out_size) {
    const float* in = (const float*)d_in[0];
    float* out = (float*)d_out;
    unsigned int n8 = (unsigned int)(out_size / 8);       // 16777216 v8 slots
    unsigned int grid = n8 / (BLOCK * VPT8);              // 32768 blocks (exact)
    alibi_add_kernel<<<grid, BLOCK>>>(in, out);
}

// round 7
// speedup vs baseline: 1.0434x; 1.0043x over previous
#include <cuda_runtime.h>
#include <cuda_bf16.h>

// out[b,h,i,j] = in[b,h,i,j] + slope[h] * (j - (S-1)),  slope[h] = 2^(-0.5*(h+1))
// Shape: (2, 16, 2048, 2048) fp32. Pure HBM-streaming elementwise add.
//
// R7 (final): 256-bit accesses, .cs loads / .wb stores, VPT8=2, 256 thr,
//             32768 blocks. h/slope hoisted (block-uniform: one block = 2
//             rows of a single head plane).

static constexpr int SEQ = 2048;
static constexpr unsigned int ROW_MASK8 = (SEQ / 8) - 1;  // v8 slots per row
static constexpr int HEAD_SHIFT8 = 22 - 3;   // head plane = 2^19 v8 slots
static constexpr int HEAD_MASK = 15;
static constexpr int VPT8 = 2;               // 32B slots per thread
static constexpr unsigned int BLOCK = 256;

struct F8 { float a0,a1,a2,a3,a4,a5,a6,a7; };

__device__ __forceinline__ F8 ldg_cs_v8(const float* p) {
    F8 r;
    asm volatile("ld.global.cs.v8.f32 {%0,%1,%2,%3,%4,%5,%6,%7}, [%8];"
                 : "=f"(r.a0), "=f"(r.a1), "=f"(r.a2), "=f"(r.a3),
                   "=f"(r.a4), "=f"(r.a5), "=f"(r.a6), "=f"(r.a7)
                 : "l"(p));
    return r;
}

__device__ __forceinline__ void stg_wb_v8(float* p, const F8& r) {
    asm volatile("st.global.v8.f32 [%0], {%1,%2,%3,%4,%5,%6,%7,%8};"
                 :: "l"(p),
                    "f"(r.a0), "f"(r.a1), "f"(r.a2), "f"(r.a3),
                    "f"(r.a4), "f"(r.a5), "f"(r.a6), "f"(r.a7)
                 : "memory");
}

__global__ void __launch_bounds__(256)
alibi_add_kernel(const float* __restrict__ in, float* __restrict__ out) {
    unsigned int base = blockIdx.x * (BLOCK * VPT8) + threadIdx.x;

    // Block spans 512 v8-slots = 2 full rows of one head plane -> h uniform.
    int h = (int)((base >> HEAD_SHIFT8) & HEAD_MASK);
    float slope = exp2f(-0.5f * (float)(h + 1));

    F8 v[VPT8];
#pragma unroll
    for (int k = 0; k < VPT8; k++) {
        v[k] = ldg_cs_v8(in + (unsigned long long)(base + k * BLOCK) * 8ull);
    }

#pragma unroll
    for (int k = 0; k < VPT8; k++) {
        unsigned int slot = base + k * BLOCK;
        int j8 = (int)(slot & ROW_MASK8);
        float d0 = (float)(j8 * 8 - (SEQ - 1));

        F8 r = v[k];
        r.a0 = fmaf(slope, d0,        r.a0);
        r.a1 = fmaf(slope, d0 + 1.0f, r.a1);
        r.a2 = fmaf(slope, d0 + 2.0f, r.a2);
        r.a3 = fmaf(slope, d0 + 3.0f, r.a3);
        r.a4 = fmaf(slope, d0 + 4.0f, r.a4);
        r.a5 = fmaf(slope, d0 + 5.0f, r.a5);
        r.a6 = fmaf(slope, d0 + 6.0f, r.a6);
        r.a7 = fmaf(slope, d0 + 7.0f, r.a7);
        stg_wb_v8(out + (unsigned long long)slot * 8ull, r);
    }
}

extern "C" void kernel_launch(void* const* d_in, const int* in_sizes, int n_in,
                              void* d_out, int out_size) {
    const float* in = (const float*)d_in[0];
    float* out = (float*)d_out;
    unsigned int n8 = (unsigned int)(out_size / 8);       // 16777216 v8 slots
    unsigned int grid = n8 / (BLOCK * VPT8);              // 32768 blocks (exact)
    alibi_add_kernel<<<grid, BLOCK>>>(in, out);
}

// round 8
// speedup vs baseline: 1.0451x; 1.0016x over previous
#include <cuda_runtime.h>
#include <cuda_bf16.h>

// out[b,h,i,j] = in[b,h,i,j] + slope[h] * (j - (S-1)),  slope[h] = 2^(-0.5*(h+1))
// Shape: (2, 16, 2048, 2048) fp32. Pure HBM-streaming elementwise add.
//
// R8 (final sweep): 512-thread blocks, VPT8=2 (16 floats/thread), 16384
//     blocks — each block covers one contiguous 64KB span = 4 rows of one
//     head plane. 256-bit accesses, .cs loads, .wb stores, hoisted slope.

static constexpr int SEQ = 2048;
static constexpr unsigned int ROW_MASK8 = (SEQ / 8) - 1;  // v8 slots per row
static constexpr int HEAD_SHIFT8 = 22 - 3;   // head plane = 2^19 v8 slots
static constexpr int HEAD_MASK = 15;
static constexpr int VPT8 = 2;               // 32B slots per thread
static constexpr unsigned int BLOCK = 512;

struct F8 { float a0,a1,a2,a3,a4,a5,a6,a7; };

__device__ __forceinline__ F8 ldg_cs_v8(const float* p) {
    F8 r;
    asm volatile("ld.global.cs.v8.f32 {%0,%1,%2,%3,%4,%5,%6,%7}, [%8];"
                 : "=f"(r.a0), "=f"(r.a1), "=f"(r.a2), "=f"(r.a3),
                   "=f"(r.a4), "=f"(r.a5), "=f"(r.a6), "=f"(r.a7)
                 : "l"(p));
    return r;
}

__device__ __forceinline__ void stg_wb_v8(float* p, const F8& r) {
    asm volatile("st.global.v8.f32 [%0], {%1,%2,%3,%4,%5,%6,%7,%8};"
                 :: "l"(p),
                    "f"(r.a0), "f"(r.a1), "f"(r.a2), "f"(r.a3),
                    "f"(r.a4), "f"(r.a5), "f"(r.a6), "f"(r.a7)
                 : "memory");
}

__global__ void __launch_bounds__(512)
alibi_add_kernel(const float* __restrict__ in, float* __restrict__ out) {
    unsigned int base = blockIdx.x * (BLOCK * VPT8) + threadIdx.x;

    // Block spans 1024 v8-slots = 4 full rows of one head plane -> h uniform.
    int h = (int)((base >> HEAD_SHIFT8) & HEAD_MASK);
    float slope = exp2f(-0.5f * (float)(h + 1));

    F8 v[VPT8];
#pragma unroll
    for (int k = 0; k < VPT8; k++) {
        v[k] = ldg_cs_v8(in + (unsigned long long)(base + k * BLOCK) * 8ull);
    }

#pragma unroll
    for (int k = 0; k < VPT8; k++) {
        unsigned int slot = base + k * BLOCK;
        int j8 = (int)(slot & ROW_MASK8);
        float d0 = (float)(j8 * 8 - (SEQ - 1));

        F8 r = v[k];
        r.a0 = fmaf(slope, d0,        r.a0);
        r.a1 = fmaf(slope, d0 + 1.0f, r.a1);
        r.a2 = fmaf(slope, d0 + 2.0f, r.a2);
        r.a3 = fmaf(slope, d0 + 3.0f, r.a3);
        r.a4 = fmaf(slope, d0 + 4.0f, r.a4);
        r.a5 = fmaf(slope, d0 + 5.0f, r.a5);
        r.a6 = fmaf(slope, d0 + 6.0f, r.a6);
        r.a7 = fmaf(slope, d0 + 7.0f, r.a7);
        stg_wb_v8(out + (unsigned long long)slot * 8ull, r);
    }
}

extern "C" void kernel_launch(void* const* d_in, const int* in_sizes, int n_in,
                              void* d_out, int out_size) {
    const float* in = (const float*)d_in[0];
    float* out = (float*)d_out;
    unsigned int n8 = (unsigned int)(out_size / 8);       // 16777216 v8 slots
    unsigned int grid = n8 / (BLOCK * VPT8);              // 16384 blocks (exact)
    alibi_add_kernel<<<grid, BLOCK>>>(in, out);
}